// round 9
// baseline (speedup 1.0000x reference)
#include <cuda_runtime.h>
#include <cuda_bf16.h>
#include <cstdint>

// ============================================================================
// ScorePredictor: per-edge 3-layer MLP via mma.sync m16n8k16 bf16 (HMMA).
//   h1 = relu(concat(x[src],x[dst],e) @ W1^T + b1)   [E,192]->[E,64]
//   h2 = relu(h1 @ W2^T + b2)                        [E,64] ->[E,64]
//   out = h2 @ W3^T + b3                             [E,64] ->[E,1]
// Persistent grid (304 CTAs, 2/SM on 152 SMs), 128-edge tiles, 8 warps x 16
// rows. h1 = relu(c1+b1) converted to layer-2 A fragments entirely in
// registers (m16n8k16 accumulator layout == A-operand layout). W2 fragments
// register-resident. Touch-once traffic (e, src, dst, out) uses streaming
// cache policy (__ldcs/__stcs) so the reused 25.6MB node table x stays
// L2-resident against the 320MB e-stream.
// ============================================================================

static constexpr int TILE_M  = 128;
static constexpr int THREADS = 256;
static constexpr int GRID    = 304;

// SMEM offsets (bytes). A tile [128 x 192] bf16, 384 B/row.
static constexpr int SM_A  = 0;                   // 49152
static constexpr int SM_W1 = 49152;               // [64 x 192] bf16 = 24576
static constexpr int SM_W2 = SM_W1 + 24576;       // [64 x 64] bf16 = 8192
static constexpr int SM_B1 = SM_W2 + 8192;        // 64 f32
static constexpr int SM_B2 = SM_B1 + 256;         // 64 f32
static constexpr int SM_W3 = SM_B2 + 256;         // 64 f32
static constexpr int SMEM_TOTAL = SM_W3 + 256;    // 82688 -> 2 CTAs/SM

// XOR swizzle on 16B chunks within each 128B-aligned group:
// phys_chunk = (chunk & ~7) | ((chunk ^ row) & 7). Conflict-free for
// ldmatrix (8 consecutive rows -> 8 distinct bank quads) and vector stores.
__device__ __forceinline__ uint32_t swz(uint32_t row, uint32_t chunk) {
    return (chunk & ~7u) | ((chunk ^ row) & 7u);
}

__device__ __forceinline__ uint32_t smem_u32(const void* p) {
    uint32_t a;
    asm("{ .reg .u64 t; cvta.to.shared.u64 t, %1; cvt.u32.u64 %0, t; }"
        : "=r"(a) : "l"(p));
    return a;
}

__device__ __forceinline__ void ldsm_x4(uint32_t* r, uint32_t addr) {
    asm volatile("ldmatrix.sync.aligned.m8n8.x4.shared.b16 {%0,%1,%2,%3}, [%4];"
                 : "=r"(r[0]), "=r"(r[1]), "=r"(r[2]), "=r"(r[3]) : "r"(addr));
}

__device__ __forceinline__ void mma_bf16(float* c, const uint32_t* a,
                                         const uint32_t* b) {
    asm volatile(
        "mma.sync.aligned.m16n8k16.row.col.f32.bf16.bf16.f32 "
        "{%0,%1,%2,%3}, {%4,%5,%6,%7}, {%8,%9}, {%0,%1,%2,%3};"
        : "+f"(c[0]), "+f"(c[1]), "+f"(c[2]), "+f"(c[3])
        : "r"(a[0]), "r"(a[1]), "r"(a[2]), "r"(a[3]), "r"(b[0]), "r"(b[1]));
}

__device__ __forceinline__ uint32_t pack_bf16x2(float lo, float hi) {
    __nv_bfloat162 h = __floats2bfloat162_rn(lo, hi);
    return *reinterpret_cast<uint32_t*>(&h);
}

// streaming (evict-first) float4 load / int load / float store
__device__ __forceinline__ float4 ldcs_f4(const float4* p) {
    float4 v;
    asm volatile("ld.global.cs.v4.f32 {%0,%1,%2,%3}, [%4];"
                 : "=f"(v.x), "=f"(v.y), "=f"(v.z), "=f"(v.w) : "l"(p));
    return v;
}
__device__ __forceinline__ int ldcs_i32(const int* p) {
    int v;
    asm volatile("ld.global.cs.b32 %0, [%1];" : "=r"(v) : "l"(p));
    return v;
}
__device__ __forceinline__ void stcs_f32(float* p, float v) {
    asm volatile("st.global.cs.f32 [%0], %1;" :: "l"(p), "f"(v));
}

// ---------------------------------------------------------------------------
__global__ void __launch_bounds__(THREADS, 2)
score_kernel(const float* __restrict__ x, const float* __restrict__ e,
             const int* __restrict__ src, const int* __restrict__ dst,
             const float* __restrict__ W1, const float* __restrict__ b1,
             const float* __restrict__ W2, const float* __restrict__ b2,
             const float* __restrict__ W3, const float* __restrict__ b3,
             float* __restrict__ out, int n_edges) {
    extern __shared__ char smem[];
    const uint32_t sb = smem_u32(smem);
    const int tid = threadIdx.x;
    const int w   = tid >> 5;       // warp 0..7
    const int l   = tid & 31;       // lane
    const int lb  = l & 15;         // ldmatrix x4 A-row selector

    // ---- one-time: convert weights to bf16 swizzled smem tiles ----
    for (int idx = tid; idx < 64 * 192; idx += THREADS) {
        int n = idx / 192, k = idx % 192;
        uint32_t off = n * 384 + swz(n, k >> 3) * 16 + (k & 7) * 2;
        *reinterpret_cast<__nv_bfloat16*>(smem + SM_W1 + off) = __float2bfloat16(W1[idx]);
    }
    for (int idx = tid; idx < 64 * 64; idx += THREADS) {
        int n = idx >> 6, k = idx & 63;
        uint32_t off = n * 128 + swz(n, k >> 3) * 16 + (k & 7) * 2;
        *reinterpret_cast<__nv_bfloat16*>(smem + SM_W2 + off) = __float2bfloat16(W2[idx]);
    }
    if (tid < 64) {
        reinterpret_cast<float*>(smem + SM_B1)[tid] = b1[tid];
        reinterpret_cast<float*>(smem + SM_B2)[tid] = b2[tid];
        reinterpret_cast<float*>(smem + SM_W3)[tid] = W3[tid];
    }
    const float b3v = __ldg(b3);
    __syncthreads();

    const float* b1s = reinterpret_cast<const float*>(smem + SM_B1);
    const float* b2s = reinterpret_cast<const float*>(smem + SM_B2);
    const float* w3s = reinterpret_cast<const float*>(smem + SM_W3);

    // ldmatrix source coords (constant per thread)
    const uint32_t a_row  = (uint32_t)(w * 16 + lb);
    const uint32_t a_coff = (uint32_t)(l >> 4);          // 0: k0-7, 1: k8-15
    // B x4 mapping: matrices {nt klo, nt khi, nt+1 klo, nt+1 khi}
    const uint32_t bq_row = (uint32_t)((l >> 4) * 8 + (l & 7)); // + nt*8 = brow
    const uint32_t b_coff = (uint32_t)((l >> 3) & 1);

    // ---- W2 B-fragments: register-resident, loaded once per CTA (x4) ----
    uint32_t w2f[4][8][2];
#pragma unroll
    for (int k = 0; k < 4; k++)
#pragma unroll
        for (int nt = 0; nt < 8; nt += 2) {
            uint32_t r4[4];
            uint32_t brow = nt * 8 + bq_row;
            ldsm_x4(r4, sb + SM_W2 + brow * 128 + swz(brow, 2 * k + b_coff) * 16);
            w2f[k][nt][0] = r4[0];     w2f[k][nt][1] = r4[1];
            w2f[k][nt + 1][0] = r4[2]; w2f[k][nt + 1][1] = r4[3];
        }

    const int num_tiles = (n_edges + TILE_M - 1) / TILE_M;
    const int grow = tid >> 1;      // gather: edge row (2 threads/row)
    const int half = tid & 1;       // which 32-col half of each 64-wide feature
    const int q    = l & 3;         // accumulator column quad

    // prefetched indices for the current tile (streamed: touch-once)
    int cur_eidx = blockIdx.x * TILE_M + grow;
    if (cur_eidx >= n_edges) cur_eidx = 0;
    int cur_s = (blockIdx.x < num_tiles) ? ldcs_i32(src + cur_eidx) : 0;
    int cur_d = (blockIdx.x < num_tiles) ? ldcs_i32(dst + cur_eidx) : 0;

    for (int tile = blockIdx.x; tile < num_tiles; tile += gridDim.x) {
        const int base = tile * TILE_M;

        // ---- gather + fp32->bf16 into swizzled A tile [128 x 192] ----
        {
            const int eidx = cur_eidx;
            const float4* ps = reinterpret_cast<const float4*>(x + (size_t)cur_s * 64) + half * 8;
            const float4* pd = reinterpret_cast<const float4*>(x + (size_t)cur_d * 64) + half * 8;
            const float4* pe = reinterpret_cast<const float4*>(e + (size_t)eidx * 64) + half * 8;
            char* arow = smem + SM_A + grow * 384;
            const uint32_t cs = 4 * half;          // chunk offset within feature
#pragma unroll
            for (int c = 0; c < 4; c++) {
                float4 f0 = ps[c * 2], f1 = ps[c * 2 + 1];   // x: cache-all
                uint4 v;
                v.x = pack_bf16x2(f0.x, f0.y); v.y = pack_bf16x2(f0.z, f0.w);
                v.z = pack_bf16x2(f1.x, f1.y); v.w = pack_bf16x2(f1.z, f1.w);
                *reinterpret_cast<uint4*>(arow + swz(grow, cs + c) * 16) = v;

                float4 g0 = pd[c * 2], g1 = pd[c * 2 + 1];   // x: cache-all
                v.x = pack_bf16x2(g0.x, g0.y); v.y = pack_bf16x2(g0.z, g0.w);
                v.z = pack_bf16x2(g1.x, g1.y); v.w = pack_bf16x2(g1.z, g1.w);
                *reinterpret_cast<uint4*>(arow + swz(grow, 8 + cs + c) * 16) = v;

                float4 h0 = ldcs_f4(pe + c * 2);             // e: streaming
                float4 h1 = ldcs_f4(pe + c * 2 + 1);
                v.x = pack_bf16x2(h0.x, h0.y); v.y = pack_bf16x2(h0.z, h0.w);
                v.z = pack_bf16x2(h1.x, h1.y); v.w = pack_bf16x2(h1.z, h1.w);
                *reinterpret_cast<uint4*>(arow + swz(grow, 16 + cs + c) * 16) = v;
            }
        }
        __syncthreads();   // A tile complete -> all warps may read

        // ---- prefetch next tile's indices (L2 latency hides behind compute)
        {
            const int ntile = tile + gridDim.x;
            if (ntile < num_tiles) {
                int ne = ntile * TILE_M + grow;
                if (ne >= n_edges) ne = 0;
                cur_eidx = ne;
                cur_s = ldcs_i32(src + ne);
                cur_d = ldcs_i32(dst + ne);
            }
        }

        // ---- layer 1: c1[16m x 64n] = A[16m x 192k] @ W1^T ----
        float c1[8][4];
#pragma unroll
        for (int nt = 0; nt < 8; nt++)
#pragma unroll
            for (int j = 0; j < 4; j++) c1[nt][j] = 0.0f;

#pragma unroll
        for (int k = 0; k < 12; k++) {
            uint32_t af[4];
            ldsm_x4(af, sb + SM_A + a_row * 384 + swz(a_row, 2 * k + a_coff) * 16);
#pragma unroll
            for (int nt = 0; nt < 8; nt += 2) {
                uint32_t bf4[4];
                uint32_t brow = nt * 8 + bq_row;
                ldsm_x4(bf4, sb + SM_W1 + brow * 384 + swz(brow, 2 * k + b_coff) * 16);
                mma_bf16(c1[nt],     af, bf4);
                mma_bf16(c1[nt + 1], af, bf4 + 2);
            }
        }
        __syncthreads();   // all warps done reading A -> next gather may write

        // ---- fuse: h1 = relu(c1 + b1) packed DIRECTLY into layer-2 A frags.
        // m16n8k16 accumulator layout == A-operand layout:
        //   af[kt] = { c1[2kt][0..1], c1[2kt][2..3],
        //              c1[2kt+1][0..1], c1[2kt+1][2..3] } after bias+relu.
        uint32_t h1f[4][4];
#pragma unroll
        for (int kt = 0; kt < 4; kt++) {
            const int c0 = kt * 16 + 2 * q;        // cols of nt = 2kt
            const int c1i = kt * 16 + 8 + 2 * q;   // cols of nt = 2kt+1
            const float b00 = b1s[c0],  b01 = b1s[c0 + 1];
            const float b10 = b1s[c1i], b11 = b1s[c1i + 1];
            h1f[kt][0] = pack_bf16x2(fmaxf(c1[2 * kt][0] + b00, 0.0f),
                                     fmaxf(c1[2 * kt][1] + b01, 0.0f));
            h1f[kt][1] = pack_bf16x2(fmaxf(c1[2 * kt][2] + b00, 0.0f),
                                     fmaxf(c1[2 * kt][3] + b01, 0.0f));
            h1f[kt][2] = pack_bf16x2(fmaxf(c1[2 * kt + 1][0] + b10, 0.0f),
                                     fmaxf(c1[2 * kt + 1][1] + b11, 0.0f));
            h1f[kt][3] = pack_bf16x2(fmaxf(c1[2 * kt + 1][2] + b10, 0.0f),
                                     fmaxf(c1[2 * kt + 1][3] + b11, 0.0f));
        }

        // ---- layer 2: c2 = h1 @ W2^T, all operands in registers ----
        float c2[8][4];
#pragma unroll
        for (int nt = 0; nt < 8; nt++)
#pragma unroll
            for (int j = 0; j < 4; j++) c2[nt][j] = 0.0f;

#pragma unroll
        for (int kt = 0; kt < 4; kt++)
#pragma unroll
            for (int nt = 0; nt < 8; nt++)
                mma_bf16(c2[nt], h1f[kt], w2f[kt][nt]);

        // ---- layer 3: out[m] = relu(c2 + b2) . W3 + b3 (in-register) ----
        {
            float s0 = 0.0f, s1 = 0.0f;
#pragma unroll
            for (int nt = 0; nt < 8; nt++) {
                const int col = nt * 8 + 2 * q;
                const float bb0 = b2s[col], bb1 = b2s[col + 1];
                const float w30 = w3s[col], w31 = w3s[col + 1];
                s0 = fmaf(fmaxf(c2[nt][0] + bb0, 0.0f), w30, s0);
                s0 = fmaf(fmaxf(c2[nt][1] + bb1, 0.0f), w31, s0);
                s1 = fmaf(fmaxf(c2[nt][2] + bb0, 0.0f), w30, s1);
                s1 = fmaf(fmaxf(c2[nt][3] + bb1, 0.0f), w31, s1);
            }
            s0 += __shfl_xor_sync(0xffffffffu, s0, 1);
            s0 += __shfl_xor_sync(0xffffffffu, s0, 2);
            s1 += __shfl_xor_sync(0xffffffffu, s1, 1);
            s1 += __shfl_xor_sync(0xffffffffu, s1, 2);
            if (q == 0) {
                const int m0 = base + w * 16 + (l >> 2);
                if (m0 < n_edges)     stcs_f32(out + m0, s0 + b3v);
                if (m0 + 8 < n_edges) stcs_f32(out + m0 + 8, s1 + b3v);
            }
        }
        // no end-of-tile barrier: layers 2-3 touch no shared state; the
        // top-of-loop gather is fenced by the post-layer-1 __syncthreads.
    }
}

// ---------------------------------------------------------------------------
extern "C" void kernel_launch(void* const* d_in, const int* in_sizes, int n_in,
                              void* d_out, int out_size) {
    const float* x   = (const float*)d_in[0];
    const float* e   = (const float*)d_in[1];
    const int*   src = (const int*)d_in[2];
    const int*   dst = (const int*)d_in[3];
    const float* W1  = (const float*)d_in[4];
    const float* b1  = (const float*)d_in[5];
    const float* W2  = (const float*)d_in[6];
    const float* b2  = (const float*)d_in[7];
    const float* W3  = (const float*)d_in[8];
    const float* b3  = (const float*)d_in[9];
    const int n_edges = in_sizes[2];

    cudaFuncSetAttribute(score_kernel, cudaFuncAttributeMaxDynamicSharedMemorySize,
                         SMEM_TOTAL);
    score_kernel<<<GRID, THREADS, SMEM_TOTAL>>>(x, e, src, dst, W1, b1, W2, b2,
                                                W3, b3, (float*)d_out, n_edges);
}

// round 16
// speedup vs baseline: 1.9353x; 1.9353x over previous
#include <cuda_runtime.h>
#include <cuda_bf16.h>
#include <cstdint>

// ============================================================================
// ScorePredictor: per-edge 3-layer MLP via mma.sync m16n8k16 bf16 (HMMA).
//   h1 = relu(concat(x[src],x[dst],e) @ W1^T + b1)   [E,192]->[E,64]
//   h2 = relu(h1 @ W2^T + b2)                        [E,64] ->[E,64]
//   out = h2 @ W3^T + b3                             [E,64] ->[E,1]
// Persistent grid (304 CTAs, 2/SM), 128-edge tiles, 8 warps x 16 rows.
// R9 profile: L1TEX 89% SOL (scattered gather). Fixes stacked since:
//  - cooperative coalesced gather (8 lanes x contiguous bytes per row),
//    with 2-group load batching for >=6 outstanding LDGs (MLP)
//  - x pre-converted ONCE to a bf16 __device__ table: halves x gather bytes
//    at L2 AND L1 lines per LDG (128B/row), removes per-tile f32->bf16 work
//  - h1 kept in registers (mma accumulator layout == A-operand layout)
//  - W2 fragments register-resident; e/src/dst/out streaming cache policy
// ============================================================================

static constexpr int TILE_M  = 128;
static constexpr int THREADS = 256;
static constexpr int GRID    = 304;
static constexpr int MAX_NODES = 131072;   // >= 100000 dataset nodes

// bf16 node table: MAX_NODES rows x 8 chunks of 16B (64 bf16) = 16.8MB
__device__ uint4 g_xbf[MAX_NODES * 8];

// SMEM offsets (bytes). A tile [128 x 192] bf16, 384 B/row.
static constexpr int SM_A  = 0;                   // 49152
static constexpr int SM_W1 = 49152;               // [64 x 192] bf16 = 24576
static constexpr int SM_W2 = SM_W1 + 24576;       // [64 x 64] bf16 = 8192
static constexpr int SM_B1 = SM_W2 + 8192;        // 64 f32
static constexpr int SM_B2 = SM_B1 + 256;         // 64 f32
static constexpr int SM_W3 = SM_B2 + 256;         // 64 f32
static constexpr int SMEM_TOTAL = SM_W3 + 256;    // 82688 -> 2 CTAs/SM

// XOR swizzle on 16B chunks within each 8-chunk (128B) group of a row.
__device__ __forceinline__ uint32_t swz(uint32_t row, uint32_t chunk) {
    return (chunk & ~7u) | ((chunk ^ row) & 7u);
}

__device__ __forceinline__ uint32_t smem_u32(const void* p) {
    uint32_t a;
    asm("{ .reg .u64 t; cvta.to.shared.u64 t, %1; cvt.u32.u64 %0, t; }"
        : "=r"(a) : "l"(p));
    return a;
}

__device__ __forceinline__ void ldsm_x4(uint32_t* r, uint32_t addr) {
    asm volatile("ldmatrix.sync.aligned.m8n8.x4.shared.b16 {%0,%1,%2,%3}, [%4];"
                 : "=r"(r[0]), "=r"(r[1]), "=r"(r[2]), "=r"(r[3]) : "r"(addr));
}

__device__ __forceinline__ void mma_bf16(float* c, const uint32_t* a,
                                         const uint32_t* b) {
    asm volatile(
        "mma.sync.aligned.m16n8k16.row.col.f32.bf16.bf16.f32 "
        "{%0,%1,%2,%3}, {%4,%5,%6,%7}, {%8,%9}, {%0,%1,%2,%3};"
        : "+f"(c[0]), "+f"(c[1]), "+f"(c[2]), "+f"(c[3])
        : "r"(a[0]), "r"(a[1]), "r"(a[2]), "r"(a[3]), "r"(b[0]), "r"(b[1]));
}

__device__ __forceinline__ uint32_t pack_bf16x2(float lo, float hi) {
    __nv_bfloat162 h = __floats2bfloat162_rn(lo, hi);
    return *reinterpret_cast<uint32_t*>(&h);
}

// streaming (evict-first) loads/stores for touch-once data
__device__ __forceinline__ float4 ldcs_f4(const float4* p) {
    float4 v;
    asm volatile("ld.global.cs.v4.f32 {%0,%1,%2,%3}, [%4];"
                 : "=f"(v.x), "=f"(v.y), "=f"(v.z), "=f"(v.w) : "l"(p));
    return v;
}
__device__ __forceinline__ int ldcs_i32(const int* p) {
    int v;
    asm volatile("ld.global.cs.b32 %0, [%1];" : "=r"(v) : "l"(p));
    return v;
}
__device__ __forceinline__ void stcs_f32(float* p, float v) {
    asm volatile("st.global.cs.f32 [%0], %1;" :: "l"(p), "f"(v));
}

// pack two float4 (8 consecutive floats) into one 16B bf16 chunk
__device__ __forceinline__ uint4 pack8(float4 a, float4 b) {
    uint4 v;
    v.x = pack_bf16x2(a.x, a.y); v.y = pack_bf16x2(a.z, a.w);
    v.z = pack_bf16x2(b.x, b.y); v.w = pack_bf16x2(b.z, b.w);
    return v;
}

// ---------------------------------------------------------------------------
// pre-pass: x [n_nodes x 64] f32 -> g_xbf bf16 chunks (one chunk per thread).
// f32 x is touch-once -> streaming loads keep L2 free for the bf16 table.
__global__ void convert_x_kernel(const float* __restrict__ x, int n_chunks) {
    int i = blockIdx.x * blockDim.x + threadIdx.x;
    if (i >= n_chunks) return;
    const float4* p = reinterpret_cast<const float4*>(x) + 2 * (size_t)i;
    g_xbf[i] = pack8(ldcs_f4(p), ldcs_f4(p + 1));
}

// ---------------------------------------------------------------------------
__global__ void __launch_bounds__(THREADS, 2)
score_kernel(const float* __restrict__ e,
             const int* __restrict__ src, const int* __restrict__ dst,
             const float* __restrict__ W1, const float* __restrict__ b1,
             const float* __restrict__ W2, const float* __restrict__ b2,
             const float* __restrict__ W3, const float* __restrict__ b3,
             float* __restrict__ out, int n_edges) {
    extern __shared__ char smem[];
    const uint32_t sb = smem_u32(smem);
    const int tid = threadIdx.x;
    const int w   = tid >> 5;       // warp 0..7
    const int l   = tid & 31;       // lane
    const int lb  = l & 15;         // ldmatrix x4 A-row selector / index row

    // ---- one-time: convert weights to bf16 swizzled smem tiles ----
    for (int idx = tid; idx < 64 * 192; idx += THREADS) {
        int n = idx / 192, k = idx % 192;
        uint32_t off = n * 384 + swz(n, k >> 3) * 16 + (k & 7) * 2;
        *reinterpret_cast<__nv_bfloat16*>(smem + SM_W1 + off) = __float2bfloat16(W1[idx]);
    }
    for (int idx = tid; idx < 64 * 64; idx += THREADS) {
        int n = idx >> 6, k = idx & 63;
        uint32_t off = n * 128 + swz(n, k >> 3) * 16 + (k & 7) * 2;
        *reinterpret_cast<__nv_bfloat16*>(smem + SM_W2 + off) = __float2bfloat16(W2[idx]);
    }
    if (tid < 64) {
        reinterpret_cast<float*>(smem + SM_B1)[tid] = b1[tid];
        reinterpret_cast<float*>(smem + SM_B2)[tid] = b2[tid];
        reinterpret_cast<float*>(smem + SM_W3)[tid] = W3[tid];
    }
    const float b3v = __ldg(b3);
    __syncthreads();

    const float* b1s = reinterpret_cast<const float*>(smem + SM_B1);
    const float* b2s = reinterpret_cast<const float*>(smem + SM_B2);
    const float* w3s = reinterpret_cast<const float*>(smem + SM_W3);

    // ldmatrix source coords (constant per thread)
    const uint32_t a_row  = (uint32_t)(w * 16 + lb);
    const uint32_t a_coff = (uint32_t)(l >> 4);          // 0: k0-7, 1: k8-15
    const uint32_t bq_row = (uint32_t)((l >> 4) * 8 + (l & 7)); // + nt*8
    const uint32_t b_coff = (uint32_t)((l >> 3) & 1);

    // ---- W2 B-fragments: register-resident, loaded once per CTA (x4) ----
    uint32_t w2f[4][8][2];
#pragma unroll
    for (int k = 0; k < 4; k++)
#pragma unroll
        for (int nt = 0; nt < 8; nt += 2) {
            uint32_t r4[4];
            uint32_t brow = nt * 8 + bq_row;
            ldsm_x4(r4, sb + SM_W2 + brow * 128 + swz(brow, 2 * k + b_coff) * 16);
            w2f[k][nt][0] = r4[0];     w2f[k][nt][1] = r4[1];
            w2f[k][nt + 1][0] = r4[2]; w2f[k][nt + 1][1] = r4[3];
        }

    const int num_tiles = (n_edges + TILE_M - 1) / TILE_M;
    const int rbase = w * 16;       // this warp's row block within the tile
    const int gj = l >> 3;          // row-within-4-row-group (gather)
    const int gi = l & 7;           // 16B chunk index within 128B third
    const int q  = l & 3;           // accumulator column quad

    // per-warp edge indices: lane lb holds src/dst of row (rbase+lb)
    int s16, d16;
    {
        int ne = blockIdx.x * TILE_M + rbase + lb;
        if (blockIdx.x >= num_tiles || ne >= n_edges) ne = 0;
        s16 = ldcs_i32(src + ne);
        d16 = ldcs_i32(dst + ne);
    }

    for (int tile = blockIdx.x; tile < num_tiles; tile += gridDim.x) {
        const int base = tile * TILE_M;

        // ---- coalesced gather: 4-row groups processed in PAIRS.
        // Both groups' global loads issue before either group's smem
        // stores -> >=6 LDGs outstanding (latency/MLP_eff halved).
#pragma unroll
        for (int gp = 0; gp < 2; gp++) {
            uint4  xs[2], xd[2];
            float4 e0[2], e1[2];
            uint32_t rr[2];
#pragma unroll
            for (int h = 0; h < 2; h++) {
                const int row = (gp * 2 + h) * 4 + gj;       // 0..15
                const int s = __shfl_sync(0xffffffffu, s16, row);
                const int d = __shfl_sync(0xffffffffu, d16, row);
                int erow = base + rbase + row;
                if (erow >= n_edges) erow = 0;               // tail: dup edge 0
                const float4* pe =
                    reinterpret_cast<const float4*>(e + (size_t)erow * 64);
                xs[h] = g_xbf[(size_t)s * 8 + gi];
                xd[h] = g_xbf[(size_t)d * 8 + gi];
                e0[h] = ldcs_f4(pe + 2 * gi);
                e1[h] = ldcs_f4(pe + 2 * gi + 1);
                rr[h] = (uint32_t)(rbase + row);
            }
#pragma unroll
            for (int h = 0; h < 2; h++) {
                char* arow = smem + SM_A + rr[h] * 384;
                *reinterpret_cast<uint4*>(arow + swz(rr[h], gi) * 16) = xs[h];
                *reinterpret_cast<uint4*>(arow + swz(rr[h], 8 + gi) * 16) = xd[h];
                *reinterpret_cast<uint4*>(arow + swz(rr[h], 16 + gi) * 16) =
                    pack8(e0[h], e1[h]);
            }
        }

        // ---- prefetch next tile's indices BEFORE the barrier ----
        {
            const int ntile = tile + gridDim.x;
            if (ntile < num_tiles) {
                int ne = ntile * TILE_M + rbase + lb;
                if (ne >= n_edges) ne = 0;
                s16 = ldcs_i32(src + ne);
                d16 = ldcs_i32(dst + ne);
            }
        }
        __syncthreads();   // A tile complete -> all warps may read

        // ---- layer 1: c1[16m x 64n] = A[16m x 192k] @ W1^T ----
        float c1[8][4];
#pragma unroll
        for (int nt = 0; nt < 8; nt++)
#pragma unroll
            for (int j = 0; j < 4; j++) c1[nt][j] = 0.0f;

#pragma unroll
        for (int k = 0; k < 12; k++) {
            uint32_t af[4];
            ldsm_x4(af, sb + SM_A + a_row * 384 + swz(a_row, 2 * k + a_coff) * 16);
#pragma unroll
            for (int nt = 0; nt < 8; nt += 2) {
                uint32_t bf4[4];
                uint32_t brow = nt * 8 + bq_row;
                ldsm_x4(bf4, sb + SM_W1 + brow * 384 + swz(brow, 2 * k + b_coff) * 16);
                mma_bf16(c1[nt],     af, bf4);
                mma_bf16(c1[nt + 1], af, bf4 + 2);
            }
        }
        __syncthreads();   // all warps done reading A -> next gather may write

        // ---- fuse: h1 = relu(c1 + b1) packed into layer-2 A fragments
        // (m16n8k16 accumulator layout == A-operand layout)
        uint32_t h1f[4][4];
#pragma unroll
        for (int kt = 0; kt < 4; kt++) {
            const int c0 = kt * 16 + 2 * q;
            const int c1i = kt * 16 + 8 + 2 * q;
            const float b00 = b1s[c0],  b01 = b1s[c0 + 1];
            const float b10 = b1s[c1i], b11 = b1s[c1i + 1];
            h1f[kt][0] = pack_bf16x2(fmaxf(c1[2 * kt][0] + b00, 0.0f),
                                     fmaxf(c1[2 * kt][1] + b01, 0.0f));
            h1f[kt][1] = pack_bf16x2(fmaxf(c1[2 * kt][2] + b00, 0.0f),
                                     fmaxf(c1[2 * kt][3] + b01, 0.0f));
            h1f[kt][2] = pack_bf16x2(fmaxf(c1[2 * kt + 1][0] + b10, 0.0f),
                                     fmaxf(c1[2 * kt + 1][1] + b11, 0.0f));
            h1f[kt][3] = pack_bf16x2(fmaxf(c1[2 * kt + 1][2] + b10, 0.0f),
                                     fmaxf(c1[2 * kt + 1][3] + b11, 0.0f));
        }

        // ---- layer 2: c2 = h1 @ W2^T, all operands in registers ----
        float c2[8][4];
#pragma unroll
        for (int nt = 0; nt < 8; nt++)
#pragma unroll
            for (int j = 0; j < 4; j++) c2[nt][j] = 0.0f;

#pragma unroll
        for (int kt = 0; kt < 4; kt++)
#pragma unroll
            for (int nt = 0; nt < 8; nt++)
                mma_bf16(c2[nt], h1f[kt], w2f[kt][nt]);

        // ---- layer 3: out[m] = relu(c2 + b2) . W3 + b3 (in-register) ----
        {
            float s0 = 0.0f, s1 = 0.0f;
#pragma unroll
            for (int nt = 0; nt < 8; nt++) {
                const int col = nt * 8 + 2 * q;
                const float bb0 = b2s[col], bb1 = b2s[col + 1];
                const float w30 = w3s[col], w31 = w3s[col + 1];
                s0 = fmaf(fmaxf(c2[nt][0] + bb0, 0.0f), w30, s0);
                s0 = fmaf(fmaxf(c2[nt][1] + bb1, 0.0f), w31, s0);
                s1 = fmaf(fmaxf(c2[nt][2] + bb0, 0.0f), w30, s1);
                s1 = fmaf(fmaxf(c2[nt][3] + bb1, 0.0f), w31, s1);
            }
            s0 += __shfl_xor_sync(0xffffffffu, s0, 1);
            s0 += __shfl_xor_sync(0xffffffffu, s0, 2);
            s1 += __shfl_xor_sync(0xffffffffu, s1, 1);
            s1 += __shfl_xor_sync(0xffffffffu, s1, 2);
            if (q == 0) {
                const int m0 = base + rbase + (l >> 2);
                if (m0 < n_edges)     stcs_f32(out + m0, s0 + b3v);
                if (m0 + 8 < n_edges) stcs_f32(out + m0 + 8, s1 + b3v);
            }
        }
        // no end-of-tile barrier: layers 2-3 touch no shared state.
    }
}

// ---------------------------------------------------------------------------
extern "C" void kernel_launch(void* const* d_in, const int* in_sizes, int n_in,
                              void* d_out, int out_size) {
    const float* x   = (const float*)d_in[0];
    const float* e   = (const float*)d_in[1];
    const int*   src = (const int*)d_in[2];
    const int*   dst = (const int*)d_in[3];
    const float* W1  = (const float*)d_in[4];
    const float* b1  = (const float*)d_in[5];
    const float* W2  = (const float*)d_in[6];
    const float* b2  = (const float*)d_in[7];
    const float* W3  = (const float*)d_in[8];
    const float* b3  = (const float*)d_in[9];
    const int n_edges = in_sizes[2];
    const int n_nodes = in_sizes[0] / 64;
    const int n_chunks = n_nodes * 8;

    convert_x_kernel<<<(n_chunks + 255) / 256, 256>>>(x, n_chunks);

    cudaFuncSetAttribute(score_kernel, cudaFuncAttributeMaxDynamicSharedMemorySize,
                         SMEM_TOTAL);
    score_kernel<<<GRID, THREADS, SMEM_TOTAL>>>(e, src, dst, W1, b1, W2, b2,
                                                W3, b3, (float*)d_out, n_edges);
}